// round 4
// baseline (speedup 1.0000x reference)
#include <cuda_runtime.h>
#include <cuda_bf16.h>

// PhyGate: elementwise physics gate over B rows.
// R3: 8 rows/thread -> 14 front-batched LDG.128 per thread (2x per-warp MLP).
// Occupancy experiment (R2) showed warp count is not the lever; MLP is.

struct Params {
    float dt, lin_w, lin_b;
    float p1, p2;
    float p3x, p3y, p3z;
    float p4, p5, p6;
};

__device__ __forceinline__ void phygate_row(
    float bb, float vx, float vy, float vz, float wx, float wy, float wz,
    const Params& P,
    float& ovx, float& ovy, float& ovz, float& owx, float& owy, float& owz)
{
    float z = fmaf(bb, P.lin_w, P.lin_b);
    float gate1 = 1.0f / (1.0f + __expf(-z));
    float gate2 = 1.0f - gate1;

    float r = P.p6;
    float t1 = vx - wy * r;
    float t2 = vy + wx * r;
    float inv = rsqrtf(fmaf(t1, t1, fmaf(t2, t2, 1e-6f)));
    float al = P.p4 * (1.0f + P.p5) * fabsf(vz) * inv;
    al = fminf(al, 0.4f);
    float oma = 1.0f - al;

    float vbx = fmaf(oma, vx, al * r * wy);
    float vby = fmaf(oma, vy, -(al * r) * wx);
    float vbz = -P.p5 * vz;

    float c = 1.5f * al / r;
    float om15 = 1.0f - 1.5f * al;
    float wbx = fmaf(-c, vy, om15 * wx);
    float wby = fmaf(c, vx, om15 * wy);
    float wbz = wz;

    float v2x = fmaf(gate1, vx, gate2 * vbx);
    float v2y = fmaf(gate1, vy, gate2 * vby);
    float v2z = fmaf(gate1, vz, gate2 * vbz);
    float w2x = fmaf(gate1, wx, gate2 * wbx);
    float w2y = fmaf(gate1, wy, gate2 * wby);
    float w2z = fmaf(gate1, wz, gate2 * wbz);

    float nv = sqrtf(fmaf(v2x, v2x, fmaf(v2y, v2y, v2z * v2z)));

    float cx = w2y * v2z - w2z * v2y;
    float cy = w2z * v2x - w2x * v2z;
    float cz = w2x * v2y - w2y * v2x;

    float k = -P.p1 * nv;
    float ax = fmaf(k, v2x, fmaf(P.p2, cx, P.p3x));
    float ay = fmaf(k, v2y, fmaf(P.p2, cy, P.p3y));
    float az = fmaf(k, v2z, fmaf(P.p2, cz, P.p3z - 9.81f));

    ovx = fmaf(ax, P.dt, v2x);
    ovy = fmaf(ay, P.dt, v2y);
    ovz = fmaf(az, P.dt, v2z);
    owx = w2x; owy = w2y; owz = w2z;
}

__global__ void __launch_bounds__(256)
phygate_kernel(const float* __restrict__ b,
               const float* __restrict__ v,
               const float* __restrict__ w,
               const float* __restrict__ dt,
               const float* __restrict__ lin_w,
               const float* __restrict__ lin_b,
               const float* __restrict__ p1,
               const float* __restrict__ p2,
               const float* __restrict__ p3,
               const float* __restrict__ p4,
               const float* __restrict__ p5,
               const float* __restrict__ p6,
               float* __restrict__ out, int n)
{
    Params P;
    P.dt = __ldg(dt); P.lin_w = __ldg(lin_w); P.lin_b = __ldg(lin_b);
    P.p1 = __ldg(p1); P.p2 = __ldg(p2);
    P.p3x = __ldg(p3 + 0); P.p3y = __ldg(p3 + 1); P.p3z = __ldg(p3 + 2);
    P.p4 = __ldg(p4); P.p5 = __ldg(p5); P.p6 = __ldg(p6);

    int n8 = n >> 3;  // groups of 8 rows
    int t = blockIdx.x * blockDim.x + threadIdx.x;

    if (t < n8) {
        // Front-batched loads: 2 (b) + 6 (v) + 6 (w) = 14 independent LDG.128.
        const float4* b4p = reinterpret_cast<const float4*>(b) + 2 * t;
        const float4* v4p = reinterpret_cast<const float4*>(v) + 6 * t;
        const float4* w4p = reinterpret_cast<const float4*>(w) + 6 * t;

        float4 bq[2], vq[6], wq[6];
        #pragma unroll
        for (int i = 0; i < 2; i++) bq[i] = b4p[i];
        #pragma unroll
        for (int i = 0; i < 6; i++) vq[i] = v4p[i];
        #pragma unroll
        for (int i = 0; i < 6; i++) wq[i] = w4p[i];

        const float* bv = reinterpret_cast<const float*>(bq);
        const float* vv = reinterpret_cast<const float*>(vq);
        const float* ww = reinterpret_cast<const float*>(wq);

        float4 ovq[6], owq[6];
        float* ov = reinterpret_cast<float*>(ovq);
        float* ow = reinterpret_cast<float*>(owq);

        #pragma unroll
        for (int i = 0; i < 8; i++) {
            phygate_row(bv[i], vv[3*i], vv[3*i+1], vv[3*i+2],
                        ww[3*i], ww[3*i+1], ww[3*i+2], P,
                        ov[3*i], ov[3*i+1], ov[3*i+2],
                        ow[3*i], ow[3*i+1], ow[3*i+2]);
        }

        float4* outv = reinterpret_cast<float4*>(out) + 6 * t;
        float4* outw = reinterpret_cast<float4*>(out + 3 * (size_t)n) + 6 * t;
        #pragma unroll
        for (int i = 0; i < 6; i++) outv[i] = ovq[i];
        #pragma unroll
        for (int i = 0; i < 6; i++) outw[i] = owq[i];
    }

    // Tail rows (n not divisible by 8): first threads handle them scalar.
    int tail = n & 7;
    if (t < tail) {
        int row = n8 * 8 + t;
        float ovx, ovy, ovz, owx, owy, owz;
        phygate_row(b[row], v[3*row], v[3*row+1], v[3*row+2],
                    w[3*row], w[3*row+1], w[3*row+2], P,
                    ovx, ovy, ovz, owx, owy, owz);
        out[3*row] = ovx; out[3*row+1] = ovy; out[3*row+2] = ovz;
        float* ow_base = out + 3 * (size_t)n;
        ow_base[3*row] = owx; ow_base[3*row+1] = owy; ow_base[3*row+2] = owz;
    }
}

extern "C" void kernel_launch(void* const* d_in, const int* in_sizes, int n_in,
                              void* d_out, int out_size)
{
    const float* b     = (const float*)d_in[0];
    const float* v     = (const float*)d_in[1];
    const float* w     = (const float*)d_in[2];
    const float* dt    = (const float*)d_in[3];
    const float* lin_w = (const float*)d_in[4];
    const float* lin_b = (const float*)d_in[5];
    const float* p1    = (const float*)d_in[6];
    const float* p2    = (const float*)d_in[7];
    const float* p3    = (const float*)d_in[8];
    const float* p4    = (const float*)d_in[9];
    const float* p5    = (const float*)d_in[10];
    const float* p6    = (const float*)d_in[11];

    int n = in_sizes[0];  // B rows
    int n8 = (n + 7) >> 3;
    int threads = 256;
    int blocks = (n8 + threads - 1) / threads;

    phygate_kernel<<<blocks, threads>>>(b, v, w, dt, lin_w, lin_b,
                                        p1, p2, p3, p4, p5, p6,
                                        (float*)d_out, n);
}

// round 5
// speedup vs baseline: 1.3249x; 1.3249x over previous
#include <cuda_runtime.h>
#include <cuda_bf16.h>

// PhyGate R5: 1 row/thread, scalar 32-bit loads/stores, max occupancy.
// R2-R4 showed big per-thread LDG.128 batches create L1tex queue contention
// (all pipes ~40%, nothing saturated). This is the minimum-footprint,
// maximum-warp-count corner: MLP_p1=7 small loads, ~30 regs, occ->~100%.

struct Params {
    float dt, lin_w, lin_b;
    float p1, p2;
    float p3x, p3y, p3z;
    float p4, p5, p6;
};

__device__ __forceinline__ void phygate_row(
    float bb, float vx, float vy, float vz, float wx, float wy, float wz,
    const Params& P,
    float& ovx, float& ovy, float& ovz, float& owx, float& owy, float& owz)
{
    float z = fmaf(bb, P.lin_w, P.lin_b);
    float gate1 = 1.0f / (1.0f + __expf(-z));
    float gate2 = 1.0f - gate1;

    float r = P.p6;
    float t1 = vx - wy * r;
    float t2 = vy + wx * r;
    float inv = rsqrtf(fmaf(t1, t1, fmaf(t2, t2, 1e-6f)));
    float al = P.p4 * (1.0f + P.p5) * fabsf(vz) * inv;
    al = fminf(al, 0.4f);
    float oma = 1.0f - al;

    float vbx = fmaf(oma, vx, al * r * wy);
    float vby = fmaf(oma, vy, -(al * r) * wx);
    float vbz = -P.p5 * vz;

    float c = 1.5f * al / r;
    float om15 = 1.0f - 1.5f * al;
    float wbx = fmaf(-c, vy, om15 * wx);
    float wby = fmaf(c, vx, om15 * wy);
    float wbz = wz;

    float v2x = fmaf(gate1, vx, gate2 * vbx);
    float v2y = fmaf(gate1, vy, gate2 * vby);
    float v2z = fmaf(gate1, vz, gate2 * vbz);
    float w2x = fmaf(gate1, wx, gate2 * wbx);
    float w2y = fmaf(gate1, wy, gate2 * wby);
    float w2z = fmaf(gate1, wz, gate2 * wbz);

    float nv = sqrtf(fmaf(v2x, v2x, fmaf(v2y, v2y, v2z * v2z)));

    float cx = w2y * v2z - w2z * v2y;
    float cy = w2z * v2x - w2x * v2z;
    float cz = w2x * v2y - w2y * v2x;

    float k = -P.p1 * nv;
    float ax = fmaf(k, v2x, fmaf(P.p2, cx, P.p3x));
    float ay = fmaf(k, v2y, fmaf(P.p2, cy, P.p3y));
    float az = fmaf(k, v2z, fmaf(P.p2, cz, P.p3z - 9.81f));

    ovx = fmaf(ax, P.dt, v2x);
    ovy = fmaf(ay, P.dt, v2y);
    ovz = fmaf(az, P.dt, v2z);
    owx = w2x; owy = w2y; owz = w2z;
}

__global__ void __launch_bounds__(256)
phygate_kernel(const float* __restrict__ b,
               const float* __restrict__ v,
               const float* __restrict__ w,
               const float* __restrict__ dt,
               const float* __restrict__ lin_w,
               const float* __restrict__ lin_b,
               const float* __restrict__ p1,
               const float* __restrict__ p2,
               const float* __restrict__ p3,
               const float* __restrict__ p4,
               const float* __restrict__ p5,
               const float* __restrict__ p6,
               float* __restrict__ out, int n)
{
    Params P;
    P.dt = __ldg(dt); P.lin_w = __ldg(lin_w); P.lin_b = __ldg(lin_b);
    P.p1 = __ldg(p1); P.p2 = __ldg(p2);
    P.p3x = __ldg(p3 + 0); P.p3y = __ldg(p3 + 1); P.p3z = __ldg(p3 + 2);
    P.p4 = __ldg(p4); P.p5 = __ldg(p5); P.p6 = __ldg(p6);

    int row = blockIdx.x * blockDim.x + threadIdx.x;
    if (row >= n) return;

    // 7 independent scalar loads, front-batched by ptxas.
    float bb = b[row];
    float vx = v[3*row + 0];
    float vy = v[3*row + 1];
    float vz = v[3*row + 2];
    float wx = w[3*row + 0];
    float wy = w[3*row + 1];
    float wz = w[3*row + 2];

    float ovx, ovy, ovz, owx, owy, owz;
    phygate_row(bb, vx, vy, vz, wx, wy, wz, P,
                ovx, ovy, ovz, owx, owy, owz);

    out[3*row + 0] = ovx;
    out[3*row + 1] = ovy;
    out[3*row + 2] = ovz;
    float* ow_base = out + 3 * (size_t)n;
    ow_base[3*row + 0] = owx;
    ow_base[3*row + 1] = owy;
    ow_base[3*row + 2] = owz;
}

extern "C" void kernel_launch(void* const* d_in, const int* in_sizes, int n_in,
                              void* d_out, int out_size)
{
    const float* b     = (const float*)d_in[0];
    const float* v     = (const float*)d_in[1];
    const float* w     = (const float*)d_in[2];
    const float* dt    = (const float*)d_in[3];
    const float* lin_w = (const float*)d_in[4];
    const float* lin_b = (const float*)d_in[5];
    const float* p1    = (const float*)d_in[6];
    const float* p2    = (const float*)d_in[7];
    const float* p3    = (const float*)d_in[8];
    const float* p4    = (const float*)d_in[9];
    const float* p5    = (const float*)d_in[10];
    const float* p6    = (const float*)d_in[11];

    int n = in_sizes[0];  // B rows
    int threads = 256;
    int blocks = (n + threads - 1) / threads;

    phygate_kernel<<<blocks, threads>>>(b, v, w, dt, lin_w, lin_b,
                                        p1, p2, p3, p4, p5, p6,
                                        (float*)d_out, n);
}

// round 6
// speedup vs baseline: 1.3957x; 1.0535x over previous
#include <cuda_runtime.h>
#include <cuda_bf16.h>

// PhyGate R5: 1 row/thread (R4 shape, occ 80%, 32 regs) + fast-math slimming:
// kill the two per-row FP32 divisions and the full-accuracy sqrt.
// rel_err budget 1e-3; R4 was at 3.6e-8 — huge precision headroom.

struct Params {
    float dt, lin_w, lin_b;
    float p1, p2;
    float p3x, p3y, p3zg;   // p3z - 9.81 pre-folded
    float p5, p6;
    float k45;              // p4 * (1 + p5)
    float c15_over_r;       // 1.5 / r
};

__device__ __forceinline__ float fast_rcp(float x) {
    float y;
    asm("rcp.approx.f32 %0, %1;" : "=f"(y) : "f"(x));
    return y;
}
__device__ __forceinline__ float fast_sqrt(float x) {
    float y;
    asm("sqrt.approx.f32 %0, %1;" : "=f"(y) : "f"(x));
    return y;
}

__device__ __forceinline__ void phygate_row(
    float bb, float vx, float vy, float vz, float wx, float wy, float wz,
    const Params& P,
    float& ovx, float& ovy, float& ovz, float& owx, float& owy, float& owz)
{
    float z = fmaf(bb, P.lin_w, P.lin_b);
    float gate1 = fast_rcp(1.0f + __expf(-z));   // sigmoid, approx rcp
    float gate2 = 1.0f - gate1;

    float r = P.p6;
    float t1 = vx - wy * r;
    float t2 = vy + wx * r;
    float inv = rsqrtf(fmaf(t1, t1, fmaf(t2, t2, 1e-6f)));
    float al = P.k45 * fabsf(vz) * inv;
    al = fminf(al, 0.4f);
    float oma = 1.0f - al;

    float vbx = fmaf(oma, vx, al * r * wy);
    float vby = fmaf(oma, vy, -(al * r) * wx);
    float vbz = -P.p5 * vz;

    float c = al * P.c15_over_r;                 // was 1.5*al/r (per-row div)
    float om15 = fmaf(-1.5f, al, 1.0f);
    float wbx = fmaf(-c, vy, om15 * wx);
    float wby = fmaf(c, vx, om15 * wy);
    float wbz = wz;

    float v2x = fmaf(gate1, vx, gate2 * vbx);
    float v2y = fmaf(gate1, vy, gate2 * vby);
    float v2z = fmaf(gate1, vz, gate2 * vbz);
    float w2x = fmaf(gate1, wx, gate2 * wbx);
    float w2y = fmaf(gate1, wy, gate2 * wby);
    float w2z = fmaf(gate1, wz, gate2 * wbz);

    float nv = fast_sqrt(fmaf(v2x, v2x, fmaf(v2y, v2y, v2z * v2z)));

    float cx = w2y * v2z - w2z * v2y;
    float cy = w2z * v2x - w2x * v2z;
    float cz = w2x * v2y - w2y * v2x;

    float k = -P.p1 * nv;
    float ax = fmaf(k, v2x, fmaf(P.p2, cx, P.p3x));
    float ay = fmaf(k, v2y, fmaf(P.p2, cy, P.p3y));
    float az = fmaf(k, v2z, fmaf(P.p2, cz, P.p3zg));

    ovx = fmaf(ax, P.dt, v2x);
    ovy = fmaf(ay, P.dt, v2y);
    ovz = fmaf(az, P.dt, v2z);
    owx = w2x; owy = w2y; owz = w2z;
}

__global__ void __launch_bounds__(256)
phygate_kernel(const float* __restrict__ b,
               const float* __restrict__ v,
               const float* __restrict__ w,
               const float* __restrict__ dt,
               const float* __restrict__ lin_w,
               const float* __restrict__ lin_b,
               const float* __restrict__ p1,
               const float* __restrict__ p2,
               const float* __restrict__ p3,
               const float* __restrict__ p4,
               const float* __restrict__ p5,
               const float* __restrict__ p6,
               float* __restrict__ out, int n)
{
    Params P;
    P.dt = __ldg(dt); P.lin_w = __ldg(lin_w); P.lin_b = __ldg(lin_b);
    P.p1 = __ldg(p1); P.p2 = __ldg(p2);
    P.p3x = __ldg(p3 + 0); P.p3y = __ldg(p3 + 1); P.p3zg = __ldg(p3 + 2) - 9.81f;
    float p4v = __ldg(p4);
    P.p5 = __ldg(p5); P.p6 = __ldg(p6);
    P.k45 = p4v * (1.0f + P.p5);        // hoisted uniform
    P.c15_over_r = 1.5f / P.p6;         // hoisted uniform division

    int row = blockIdx.x * blockDim.x + threadIdx.x;
    if (row >= n) return;

    float bb = b[row];
    float vx = v[3*row + 0];
    float vy = v[3*row + 1];
    float vz = v[3*row + 2];
    float wx = w[3*row + 0];
    float wy = w[3*row + 1];
    float wz = w[3*row + 2];

    float ovx, ovy, ovz, owx, owy, owz;
    phygate_row(bb, vx, vy, vz, wx, wy, wz, P,
                ovx, ovy, ovz, owx, owy, owz);

    out[3*row + 0] = ovx;
    out[3*row + 1] = ovy;
    out[3*row + 2] = ovz;
    float* ow_base = out + 3 * (size_t)n;
    ow_base[3*row + 0] = owx;
    ow_base[3*row + 1] = owy;
    ow_base[3*row + 2] = owz;
}

extern "C" void kernel_launch(void* const* d_in, const int* in_sizes, int n_in,
                              void* d_out, int out_size)
{
    const float* b     = (const float*)d_in[0];
    const float* v     = (const float*)d_in[1];
    const float* w     = (const float*)d_in[2];
    const float* dt    = (const float*)d_in[3];
    const float* lin_w = (const float*)d_in[4];
    const float* lin_b = (const float*)d_in[5];
    const float* p1    = (const float*)d_in[6];
    const float* p2    = (const float*)d_in[7];
    const float* p3    = (const float*)d_in[8];
    const float* p4    = (const float*)d_in[9];
    const float* p5    = (const float*)d_in[10];
    const float* p6    = (const float*)d_in[11];

    int n = in_sizes[0];  // B rows
    int threads = 256;
    int blocks = (n + threads - 1) / threads;

    phygate_kernel<<<blocks, threads>>>(b, v, w, dt, lin_w, lin_b,
                                        p1, p2, p3, p4, p5, p6,
                                        (float*)d_out, n);
}

// round 7
// speedup vs baseline: 1.4830x; 1.0625x over previous
#include <cuda_runtime.h>
#include <cuda_bf16.h>

// PhyGate R6: 2 rows/thread, float2 loads/stores.
// R4/R5 established: many-small-ops + high occ wins; issue% (58) is now a
// co-binding constraint. Halve memory instruction count per row (LDG.64/STG.64)
// without the LDG.128 mega-batching that regressed in R1/R3.

struct Params {
    float dt, lin_w, lin_b;
    float p1, p2;
    float p3x, p3y, p3zg;   // p3z - 9.81 pre-folded
    float p5, p6;
    float k45;              // p4 * (1 + p5)
    float c15_over_r;       // 1.5 / r
};

__device__ __forceinline__ float fast_rcp(float x) {
    float y;
    asm("rcp.approx.f32 %0, %1;" : "=f"(y) : "f"(x));
    return y;
}
__device__ __forceinline__ float fast_sqrt(float x) {
    float y;
    asm("sqrt.approx.f32 %0, %1;" : "=f"(y) : "f"(x));
    return y;
}

__device__ __forceinline__ void phygate_row(
    float bb, float vx, float vy, float vz, float wx, float wy, float wz,
    const Params& P,
    float& ovx, float& ovy, float& ovz, float& owx, float& owy, float& owz)
{
    float z = fmaf(bb, P.lin_w, P.lin_b);
    float gate1 = fast_rcp(1.0f + __expf(-z));
    float gate2 = 1.0f - gate1;

    float r = P.p6;
    float t1 = vx - wy * r;
    float t2 = vy + wx * r;
    float inv = rsqrtf(fmaf(t1, t1, fmaf(t2, t2, 1e-6f)));
    float al = P.k45 * fabsf(vz) * inv;
    al = fminf(al, 0.4f);
    float oma = 1.0f - al;

    float vbx = fmaf(oma, vx, al * r * wy);
    float vby = fmaf(oma, vy, -(al * r) * wx);
    float vbz = -P.p5 * vz;

    float c = al * P.c15_over_r;
    float om15 = fmaf(-1.5f, al, 1.0f);
    float wbx = fmaf(-c, vy, om15 * wx);
    float wby = fmaf(c, vx, om15 * wy);
    float wbz = wz;

    float v2x = fmaf(gate1, vx, gate2 * vbx);
    float v2y = fmaf(gate1, vy, gate2 * vby);
    float v2z = fmaf(gate1, vz, gate2 * vbz);
    float w2x = fmaf(gate1, wx, gate2 * wbx);
    float w2y = fmaf(gate1, wy, gate2 * wby);
    float w2z = fmaf(gate1, wz, gate2 * wbz);

    float nv = fast_sqrt(fmaf(v2x, v2x, fmaf(v2y, v2y, v2z * v2z)));

    float cx = w2y * v2z - w2z * v2y;
    float cy = w2z * v2x - w2x * v2z;
    float cz = w2x * v2y - w2y * v2x;

    float k = -P.p1 * nv;
    float ax = fmaf(k, v2x, fmaf(P.p2, cx, P.p3x));
    float ay = fmaf(k, v2y, fmaf(P.p2, cy, P.p3y));
    float az = fmaf(k, v2z, fmaf(P.p2, cz, P.p3zg));

    ovx = fmaf(ax, P.dt, v2x);
    ovy = fmaf(ay, P.dt, v2y);
    ovz = fmaf(az, P.dt, v2z);
    owx = w2x; owy = w2y; owz = w2z;
}

__global__ void __launch_bounds__(256)
phygate_kernel(const float* __restrict__ b,
               const float* __restrict__ v,
               const float* __restrict__ w,
               const float* __restrict__ dt,
               const float* __restrict__ lin_w,
               const float* __restrict__ lin_b,
               const float* __restrict__ p1,
               const float* __restrict__ p2,
               const float* __restrict__ p3,
               const float* __restrict__ p4,
               const float* __restrict__ p5,
               const float* __restrict__ p6,
               float* __restrict__ out, int n)
{
    Params P;
    P.dt = __ldg(dt); P.lin_w = __ldg(lin_w); P.lin_b = __ldg(lin_b);
    P.p1 = __ldg(p1); P.p2 = __ldg(p2);
    P.p3x = __ldg(p3 + 0); P.p3y = __ldg(p3 + 1); P.p3zg = __ldg(p3 + 2) - 9.81f;
    float p4v = __ldg(p4);
    P.p5 = __ldg(p5); P.p6 = __ldg(p6);
    P.k45 = p4v * (1.0f + P.p5);
    P.c15_over_r = 1.5f / P.p6;

    int n2 = n >> 1;
    int t = blockIdx.x * blockDim.x + threadIdx.x;

    if (t < n2) {
        // 8 independent LDG.64: 1 (b) + 3 (v) + 3 (w) ... b is 1 float2.
        float2 b2 = reinterpret_cast<const float2*>(b)[t];
        const float2* v2p = reinterpret_cast<const float2*>(v) + 3 * t;
        const float2* w2p = reinterpret_cast<const float2*>(w) + 3 * t;
        float2 va = v2p[0], vb = v2p[1], vc = v2p[2];
        float2 wa = w2p[0], wb = w2p[1], wc = w2p[2];

        // row0: (va.x, va.y, vb.x) / (wa.x, wa.y, wb.x)
        // row1: (vb.y, vc.x, vc.y) / (wb.y, wc.x, wc.y)
        float ov0x, ov0y, ov0z, ow0x, ow0y, ow0z;
        float ov1x, ov1y, ov1z, ow1x, ow1y, ow1z;

        phygate_row(b2.x, va.x, va.y, vb.x, wa.x, wa.y, wb.x, P,
                    ov0x, ov0y, ov0z, ow0x, ow0y, ow0z);
        phygate_row(b2.y, vb.y, vc.x, vc.y, wb.y, wc.x, wc.y, P,
                    ov1x, ov1y, ov1z, ow1x, ow1y, ow1z);

        float2* outv = reinterpret_cast<float2*>(out) + 3 * t;
        float2* outw = reinterpret_cast<float2*>(out + 3 * (size_t)n) + 3 * t;
        outv[0] = make_float2(ov0x, ov0y);
        outv[1] = make_float2(ov0z, ov1x);
        outv[2] = make_float2(ov1y, ov1z);
        outw[0] = make_float2(ow0x, ow0y);
        outw[1] = make_float2(ow0z, ow1x);
        outw[2] = make_float2(ow1y, ow1z);
    }

    // Tail row if n is odd.
    if ((n & 1) && t == 0) {
        int row = n - 1;
        float ovx, ovy, ovz, owx, owy, owz;
        phygate_row(b[row], v[3*row], v[3*row+1], v[3*row+2],
                    w[3*row], w[3*row+1], w[3*row+2], P,
                    ovx, ovy, ovz, owx, owy, owz);
        out[3*row] = ovx; out[3*row+1] = ovy; out[3*row+2] = ovz;
        float* ow_base = out + 3 * (size_t)n;
        ow_base[3*row] = owx; ow_base[3*row+1] = owy; ow_base[3*row+2] = owz;
    }
}

extern "C" void kernel_launch(void* const* d_in, const int* in_sizes, int n_in,
                              void* d_out, int out_size)
{
    const float* b     = (const float*)d_in[0];
    const float* v     = (const float*)d_in[1];
    const float* w     = (const float*)d_in[2];
    const float* dt    = (const float*)d_in[3];
    const float* lin_w = (const float*)d_in[4];
    const float* lin_b = (const float*)d_in[5];
    const float* p1    = (const float*)d_in[6];
    const float* p2    = (const float*)d_in[7];
    const float* p3    = (const float*)d_in[8];
    const float* p4    = (const float*)d_in[9];
    const float* p5    = (const float*)d_in[10];
    const float* p6    = (const float*)d_in[11];

    int n = in_sizes[0];  // B rows
    int n2 = (n + 1) >> 1;
    int threads = 256;
    int blocks = (n2 + threads - 1) / threads;

    phygate_kernel<<<blocks, threads>>>(b, v, w, dt, lin_w, lin_b,
                                        p1, p2, p3, p4, p5, p6,
                                        (float*)d_out, n);
}